// round 10
// baseline (speedup 1.0000x reference)
#include <cuda_runtime.h>
#include <cuda_bf16.h>

// Problem constants (fixed shapes from reference)
#define B_     128
#define C_     1024
#define HW_    196          // 14*14
#define VEC_   49           // 196/4 float4 per channel row
#define CHUNKS 16           // channel chunks per sample
#define CPB    64           // channels per block (C_/CHUNKS)
#define THREADS 256         // 8 warps
#define NPART  (B_*CHUNKS)  // 2048 partials (one per block)

#define MARGIN 1.0f
#define EPS    1e-6f

__device__ float g_partials[NPART];
__device__ unsigned int g_ticket = 0;   // self-resetting; replay-safe

__global__ __launch_bounds__(THREADS)
void ffl_fused_kernel(const float* __restrict__ feat,
                      const float* __restrict__ feat_p,
                      const float* __restrict__ avg_feat,   // [2,1024]
                      const int* __restrict__ qual,         // [128] int32
                      const int* __restrict__ label,        // [128] int32
                      float* __restrict__ out)
{
    const int chunk = blockIdx.x;        // 0..15
    const int b     = blockIdx.y;        // 0..127
    const int tid   = threadIdx.x;
    const int warp  = tid >> 5;          // 0..7
    const int lane  = tid & 31;

    // Select source tensor for this sample (only this one is read)
    const int q  = qual[b];
    const float* __restrict__ src = (q == 1) ? feat : feat_p;
    const int lb = label[b] & 1;   // mask: guaranteed in-bounds gather
    const float* __restrict__ af_pos = avg_feat + (size_t)lb * C_;
    const float* __restrict__ af_neg = avg_feat + (size_t)(1 - lb) * C_;

    // This warp owns 8 contiguous channels: cbase .. cbase+7
    const int cbase = chunk * CPB + warp * 8;
    const float4* __restrict__ base =
        reinterpret_cast<const float4*>(src + ((size_t)b * C_ + cbase) * HW_);

    const bool tail = (lane < VEC_ - 32);   // lanes 0..16 load the second vec

    // Pure load+add main loop: 16 independent LDG.128 per thread, no shuffles.
    float s[8];
    #pragma unroll
    for (int r = 0; r < 8; ++r) {
        const float4* __restrict__ row = base + (size_t)r * VEC_;
        float4 v0 = row[lane];
        float t = v0.x + v0.y + v0.z + v0.w;
        if (tail) {
            float4 v1 = row[lane + 32];
            t += v1.x + v1.y + v1.z + v1.w;
        }
        s[r] = t;
    }

    // One shuffle phase: 8 independent butterfly reductions (pipelined).
    #pragma unroll
    for (int off = 16; off > 0; off >>= 1) {
        #pragma unroll
        for (int r = 0; r < 8; ++r)
            s[r] += __shfl_xor_sync(0xFFFFFFFFu, s[r], off);
    }

    float acc = 0.0f;
    if (lane == 0) {
        #pragma unroll
        for (int r = 0; r < 8; ++r) {
            const int   c   = cbase + r;
            const float sel = s[r] * (1.0f / (float)HW_);
            acc += fmaxf(fabsf(sel - af_pos[c] + EPS)
                       - fabsf(sel - af_neg[c] + EPS) + MARGIN, 0.0f);
        }
    }

    // Block reduce the 8 warp-leader partials (fixed order -> deterministic)
    __shared__ float warp_acc[8];
    __shared__ bool  is_last;
    if (lane == 0) warp_acc[warp] = acc;
    __syncthreads();
    if (tid == 0) {
        float t = 0.0f;
        #pragma unroll
        for (int w = 0; w < 8; ++w) t += warp_acc[w];
        __stcg(&g_partials[b * CHUNKS + chunk], t * (1.0f / (float)C_));
        __threadfence();
        unsigned int ticket = atomicAdd(&g_ticket, 1u);
        is_last = (ticket == NPART - 1);
    }
    __syncthreads();

    // Last block to finish performs the deterministic final sum.
    if (is_last) {
        if (tid == 0) g_ticket = 0;   // reset for next graph replay
        float s2 = 0.0f;
        #pragma unroll
        for (int i = 0; i < NPART / THREADS; ++i)       // 8 each, fixed order
            s2 += __ldcg(&g_partials[tid + i * THREADS]);

        __shared__ float sm[THREADS];
        sm[tid] = s2;
        __syncthreads();
        #pragma unroll
        for (int step = THREADS / 2; step > 0; step >>= 1) {
            if (tid < step) sm[tid] += sm[tid + step];
            __syncthreads();
        }
        if (tid == 0) out[0] = sm[0];
    }
}

extern "C" void kernel_launch(void* const* d_in, const int* in_sizes, int n_in,
                              void* d_out, int out_size)
{
    const float* feat     = (const float*)d_in[0];
    const float* feat_p   = (const float*)d_in[1];
    const float* avg_feat = (const float*)d_in[2];
    const int*   qual     = (const int*)d_in[3];
    const int*   label    = (const int*)d_in[4];
    float* out = (float*)d_out;

    dim3 grid(CHUNKS, B_);
    ffl_fused_kernel<<<grid, THREADS>>>(feat, feat_p, avg_feat, qual, label, out);
}